// round 10
// baseline (speedup 1.0000x reference)
#include <cuda_runtime.h>
#include <cuda_bf16.h>
#include <cstdint>

#define MM 32768
#define KK 1024
#define NN 1024
#define NBR 5

// ------------------- static device scratch ---------------------------------
// x/W splits stored K-CHUNKED + PRE-SWIZZLED: [kc][row][64] bf16, where the
// 8x16B granules of each row are permuted by (c16 ^ (row&7)).  A 256-row x
// 64-col tile is then ONE contiguous 32KB block, bulk-copyable with the
// ldmatrix swizzle already in place (swizzle depends only on row&7).
__device__ __nv_bfloat16 g_xhi[(size_t)MM * KK];
__device__ __nv_bfloat16 g_xlo[(size_t)MM * KK];
__device__ __nv_bfloat16 g_whi[(size_t)NN * KK];
__device__ __nv_bfloat16 g_wlo[(size_t)NN * KK];
__device__ __nv_bfloat16 g_abf[80 * KK];                 // [80][1024] bf16 (row-major)
__device__ __nv_bfloat16 g_bc[(size_t)NBR * NN * 16];    // [br][n][16], scale folded
__device__ __nv_bfloat16 g_xa[(size_t)MM * 80];          // [m][80] bf16

// ------------------- helpers -----------------------------------------------
__device__ __forceinline__ uint32_t s2u(const void* p) {
    uint32_t a;
    asm("{ .reg .u64 t; cvta.to.shared.u64 t, %1; cvt.u32.u64 %0, t; }" : "=r"(a) : "l"(p));
    return a;
}
#define CPA16(d, s) asm volatile("cp.async.cg.shared.global [%0], [%1], 16;" :: "r"(d), "l"(s))
#define CPCOMMIT()  asm volatile("cp.async.commit_group;")
#define CPWAIT(n)   asm volatile("cp.async.wait_group %0;" :: "n"(n))

#define MBINIT(a, c) asm volatile("mbarrier.init.shared.b64 [%0], %1;" :: "r"(a), "r"((uint32_t)(c)) : "memory")
#define MB_EXPECT_TX(a, n) asm volatile("mbarrier.arrive.expect_tx.shared.b64 _, [%0], %1;" :: "r"(a), "r"((uint32_t)(n)) : "memory")
#define BULK_G2S(dst, src, bytes, mb) \
    asm volatile("cp.async.bulk.shared::cta.global.mbarrier::complete_tx::bytes [%0], [%1], %2, [%3];" \
                 :: "r"(dst), "l"(src), "r"((uint32_t)(bytes)), "r"(mb) : "memory")

__device__ __forceinline__ void mbar_wait(uint32_t mbar, uint32_t parity) {
    uint32_t done;
    asm volatile("{\n\t.reg .pred p;\n\t"
                 "mbarrier.try_wait.parity.acquire.cta.shared::cta.b64 p, [%1], %2;\n\t"
                 "selp.b32 %0, 1, 0, p;\n\t}"
                 : "=r"(done) : "r"(mbar), "r"(parity) : "memory");
    while (!done) {
        asm volatile("{\n\t.reg .pred p;\n\t"
                     "mbarrier.try_wait.parity.acquire.cta.shared::cta.b64 p, [%1], %2, 0x989680;\n\t"
                     "selp.b32 %0, 1, 0, p;\n\t}"
                     : "=r"(done) : "r"(mbar), "r"(parity) : "memory");
    }
}

__device__ __forceinline__ void ldsm4(uint32_t* r, uint32_t a) {
    asm volatile("ldmatrix.sync.aligned.m8n8.x4.shared.b16 {%0,%1,%2,%3}, [%4];"
                 : "=r"(r[0]), "=r"(r[1]), "=r"(r[2]), "=r"(r[3]) : "r"(a));
}
__device__ __forceinline__ void ldsm2(uint32_t* r, uint32_t a) {
    asm volatile("ldmatrix.sync.aligned.m8n8.x2.shared.b16 {%0,%1}, [%2];"
                 : "=r"(r[0]), "=r"(r[1]) : "r"(a));
}
__device__ __forceinline__ void mma16816(float* c, const uint32_t* a, uint32_t b0, uint32_t b1) {
    asm volatile("mma.sync.aligned.m16n8k16.row.col.f32.bf16.bf16.f32 "
                 "{%0,%1,%2,%3},{%4,%5,%6,%7},{%8,%9},{%0,%1,%2,%3};"
                 : "+f"(c[0]), "+f"(c[1]), "+f"(c[2]), "+f"(c[3])
                 : "r"(a[0]), "r"(a[1]), "r"(a[2]), "r"(a[3]), "r"(b0), "r"(b1));
}
__device__ __forceinline__ void split2(float v, __nv_bfloat16& h, __nv_bfloat16& l) {
    h = __float2bfloat16(v);
    l = __float2bfloat16(v - __bfloat162float(h));
}
__device__ __forceinline__ uint32_t pack2(__nv_bfloat16 a, __nv_bfloat16 b) {
    return (uint32_t)__bfloat16_as_ushort(a) | ((uint32_t)__bfloat16_as_ushort(b) << 16);
}

// ------------------- prep kernels ------------------------------------------
// Each thread handles one 16B output granule (8 elems) of one row.
// Output layout: byte offset ((kc*ROWS + r)*128) + ((c16 ^ (r&7))<<4).
__global__ void __launch_bounds__(256) split_x_k(const float* __restrict__ x) {
    size_t t = (size_t)blockIdx.x * 256 + threadIdx.x;   // < MM*128
    size_t r = t >> 7;
    int g8 = (int)(t & 127);          // granule index in row (0..127)
    int kc = g8 >> 3, c16 = g8 & 7;
    const float* src = x + r * KK + g8 * 8;
    float4 v0 = *(const float4*)src, v1 = *(const float4*)(src + 4);
    float f[8] = {v0.x, v0.y, v0.z, v0.w, v1.x, v1.y, v1.z, v1.w};
    __nv_bfloat16 hb[8], lb[8];
#pragma unroll
    for (int j = 0; j < 8; ++j) split2(f[j], hb[j], lb[j]);
    uint4 hv{pack2(hb[0], hb[1]), pack2(hb[2], hb[3]), pack2(hb[4], hb[5]), pack2(hb[6], hb[7])};
    uint4 lv{pack2(lb[0], lb[1]), pack2(lb[2], lb[3]), pack2(lb[4], lb[5]), pack2(lb[6], lb[7])};
    size_t dst = ((size_t)kc * MM + r) * 128 + ((size_t)(c16 ^ ((int)r & 7)) << 4);
    *(uint4*)((char*)g_xhi + dst) = hv;
    *(uint4*)((char*)g_xlo + dst) = lv;
}
__global__ void __launch_bounds__(256) split_w_k(const float* __restrict__ w) {
    size_t t = (size_t)blockIdx.x * 256 + threadIdx.x;   // < NN*128
    size_t r = t >> 7;
    int g8 = (int)(t & 127);
    int kc = g8 >> 3, c16 = g8 & 7;
    const float* src = w + r * KK + g8 * 8;
    float4 v0 = *(const float4*)src, v1 = *(const float4*)(src + 4);
    float f[8] = {v0.x, v0.y, v0.z, v0.w, v1.x, v1.y, v1.z, v1.w};
    __nv_bfloat16 hb[8], lb[8];
#pragma unroll
    for (int j = 0; j < 8; ++j) split2(f[j], hb[j], lb[j]);
    uint4 hv{pack2(hb[0], hb[1]), pack2(hb[2], hb[3]), pack2(hb[4], hb[5]), pack2(hb[6], hb[7])};
    uint4 lv{pack2(lb[0], lb[1]), pack2(lb[2], lb[3]), pack2(lb[4], lb[5]), pack2(lb[6], lb[7])};
    size_t dst = ((size_t)kc * NN + r) * 128 + ((size_t)(c16 ^ ((int)r & 7)) << 4);
    *(uint4*)((char*)g_whi + dst) = hv;
    *(uint4*)((char*)g_wlo + dst) = lv;
}
__global__ void __launch_bounds__(256) conv_a_k(const float* __restrict__ A_sh,
                                                const float* __restrict__ A_tasks) {
    size_t i = ((size_t)blockIdx.x * 256 + threadIdx.x) * 4;   // < 81920
    const float* src = (i < 16384) ? (A_sh + i) : (A_tasks + (i - 16384));
    float4 v = *(const float4*)src;
    __nv_bfloat162 a{__float2bfloat16(v.x), __float2bfloat16(v.y)};
    __nv_bfloat162 b{__float2bfloat16(v.z), __float2bfloat16(v.w)};
    ((__nv_bfloat162*)(g_abf + i))[0] = a; ((__nv_bfloat162*)(g_abf + i))[1] = b;
}
__global__ void __launch_bounds__(256) prep_bc_k(const float* __restrict__ B_sh,
                                                 const float* __restrict__ B_tasks,
                                                 const float* __restrict__ ts) {
    int id = blockIdx.x * 256 + threadIdx.x;   // < 5120
    int br = id >> 10, n = id & 1023;
    const float* row = (br == 0) ? (B_sh + (size_t)n * 16)
                                 : (B_tasks + ((size_t)(br - 1) * NN + n) * 16);
    float s = (br == 0) ? 1.0f : ts[br - 1];
    __nv_bfloat16* dst = g_bc + ((size_t)br * NN + n) * 16;
#pragma unroll
    for (int r = 0; r < 16; ++r) dst[r] = __float2bfloat16(s * row[r]);
}

// ------------------- XA kernel (HMMA, single bf16) --------------------------
#define XA_STG 26624

__device__ __forceinline__ void xa_load(int c, uint32_t sb, int m0, int tid) {
#pragma unroll
    for (int i = 0; i < 7; ++i) {
        int id = tid + (i << 8);
        if (id < 1024) {
            // x: chunked + pre-swizzled global layout -> raw copy
            int row = id >> 3, c16 = id & 7;
            CPA16(sb + row * 128 + (c16 << 4),
                  (const char*)g_xhi + ((size_t)c * MM + m0 + row) * 128 + c16 * 16);
        } else if (id < 1664) {
            int id2 = id - 1024;
            int row = id2 >> 3, c16 = id2 & 7;
            CPA16(sb + 16384 + row * 128 + ((c16 ^ (row & 7)) << 4),
                  (const char*)(g_abf + (size_t)row * KK + (c << 6)) + c16 * 16);
        }
    }
}

__global__ void __launch_bounds__(256, 1) xa_kernel() {
    extern __shared__ char sm[];
    const uint32_t base = s2u(sm);
    const int tid = threadIdx.x, wid = tid >> 5, l = tid & 31;
    const int m0 = blockIdx.x * 128;
    const int wm = wid & 3, wn = wid >> 2;

    float acc[2][5][4];
#pragma unroll
    for (int i = 0; i < 2; ++i)
#pragma unroll
        for (int j = 0; j < 5; ++j)
#pragma unroll
            for (int k = 0; k < 4; ++k) acc[i][j][k] = 0.f;

    xa_load(0, base, m0, tid); CPCOMMIT();
    xa_load(1, base + XA_STG, m0, tid); CPCOMMIT();

    const uint32_t arow  = (uint32_t)((wm * 32 + (l & 15)) * 128);
    const uint32_t brow  = (uint32_t)((wn * 40 + (l & 15)) * 128) + 16384;
    const uint32_t brow2 = (uint32_t)((wn * 40 + 32 + (l & 7)) * 128) + 16384;
    const uint32_t ax = (uint32_t)(l & 7);
    const uint32_t hi16 = (uint32_t)(l >> 4);
    const uint32_t sel2 = (uint32_t)((l >> 3) & 1);

    for (int c = 0; c < 16; ++c) {
        uint32_t sb = base + (c % 3) * XA_STG;
        if (c == 15) { CPWAIT(0); } else { CPWAIT(1); }
        __syncthreads();
        if (c + 2 < 16) { xa_load(c + 2, base + ((c + 2) % 3) * XA_STG, m0, tid); CPCOMMIT(); }
#pragma unroll
        for (int ks = 0; ks < 4; ++ks) {
            uint32_t kc = (uint32_t)(ks * 2);
            uint32_t a[2][4], b[2][4], b2[2];
#pragma unroll
            for (int fi = 0; fi < 2; ++fi)
                ldsm4(a[fi], sb + arow + fi * 2048 + (((kc + hi16) ^ ax) << 4));
#pragma unroll
            for (int g = 0; g < 2; ++g)
                ldsm4(b[g], sb + brow + g * 2048 + (((kc + hi16) ^ ax) << 4));
            ldsm2(b2, sb + brow2 + (((kc + sel2) ^ ax) << 4));
#pragma unroll
            for (int fi = 0; fi < 2; ++fi) {
#pragma unroll
                for (int nf = 0; nf < 4; ++nf)
                    mma16816(acc[fi][nf], a[fi], b[nf >> 1][nf & 1], b[nf >> 1][(nf & 1) + 2]);
                mma16816(acc[fi][4], a[fi], b2[0], b2[1]);
            }
        }
    }
    __syncthreads();

#pragma unroll
    for (int fi = 0; fi < 2; ++fi)
#pragma unroll
        for (int j = 0; j < 5; ++j) {
            int n = wn * 40 + j * 8 + 2 * (l & 3);
            int mlo = m0 + wm * 32 + fi * 16 + (l >> 2);
            __nv_bfloat162 v0{__float2bfloat16(acc[fi][j][0]), __float2bfloat16(acc[fi][j][1])};
            __nv_bfloat162 v1{__float2bfloat16(acc[fi][j][2]), __float2bfloat16(acc[fi][j][3])};
            *(__nv_bfloat162*)(g_xa + (size_t)mlo * 80 + n) = v0;
            *(__nv_bfloat162*)(g_xa + (size_t)(mlo + 8) * 80 + n) = v1;
        }
}

// ------------------- main kernel --------------------------------------------
// 512 threads, tile M=256 x N=128; 16 warps = 4(m) x 4(n); warp 64x32.
// 48 chunks (3 hi/lo terms x 16 K-slices).  Per chunk, TWO cp.async.bulk
// copies (X 32KB + W 16KB) into a 3-stage mbarrier ring.  Stage = 48KB.
#define M_STG 49152

__device__ __forceinline__ void corr_load(int br, uint32_t ep, int m0, int n0, int tid) {
    int row = tid >> 1, ch = tid & 1;
    uint32_t slot = (uint32_t)(((row & 3) * 2 + ch) ^ ((row >> 2) & 1));
    uint32_t off = (uint32_t)((row >> 2) * 128) + slot * 16;
    CPA16(ep + off, (const char*)(g_xa + (size_t)(m0 + row) * 80 + br * 16) + ch * 16);
    if (tid < 256)
        CPA16(ep + 8192 + off, (const char*)(g_bc + ((size_t)br * NN + n0 + row) * 16) + ch * 16);
}

__global__ void __launch_bounds__(512, 1) main_kernel(const float* __restrict__ bias,
                                                      float* __restrict__ out) {
    extern __shared__ char sm[];
    __shared__ uint64_t s_mbar[3];
    const uint32_t base = s2u(sm);
    const int tid = threadIdx.x, wid = tid >> 5, l = tid & 31;
    const int n0 = blockIdx.x * 128, m0 = blockIdx.y * 256;
    const int wm = wid & 3, wn = wid >> 2;

    if (tid == 0) { MBINIT(s2u(&s_mbar[0]), 1); MBINIT(s2u(&s_mbar[1]), 1); MBINIT(s2u(&s_mbar[2]), 1); }
    __syncthreads();

    float acc[4][4][4];
#pragma unroll
    for (int i = 0; i < 4; ++i)
#pragma unroll
        for (int j = 0; j < 4; ++j)
#pragma unroll
            for (int k = 0; k < 4; ++k) acc[i][j][k] = 0.f;

    // issue chunk c into stage c%3 (tid 0 only)
    auto issue = [&](int c) {
        int t = c >> 4, kc = c & 15;
        const char* xs = (const char*)((t == 1) ? g_xlo : g_xhi);
        const char* ws = (const char*)((t == 2) ? g_wlo : g_whi);
        uint32_t sb = base + (uint32_t)(c % 3) * M_STG;
        uint32_t mb = s2u(&s_mbar[c % 3]);
        MB_EXPECT_TX(mb, M_STG);
        BULK_G2S(sb, xs + ((size_t)kc * MM + m0) * 128, 32768, mb);
        BULK_G2S(sb + 32768, ws + ((size_t)kc * NN + n0) * 128, 16384, mb);
    };
    if (tid == 0) { issue(0); issue(1); }

    const uint32_t arow = (uint32_t)((wm * 64 + (l & 15)) * 128);
    const uint32_t brow = (uint32_t)((wn * 32 + (l & 15)) * 128) + 32768;
    const uint32_t ax = (uint32_t)(l & 7);
    const uint32_t hi16 = (uint32_t)(l >> 4);

    for (int c = 0; c < 48; ++c) {
        uint32_t sb = base + (uint32_t)(c % 3) * M_STG;
        mbar_wait(s2u(&s_mbar[c % 3]), (uint32_t)((c / 3) & 1));
#pragma unroll
        for (int ks = 0; ks < 4; ++ks) {
            uint32_t kc = (uint32_t)(ks * 2);
            uint32_t a[4][4], b[2][4];
#pragma unroll
            for (int fi = 0; fi < 4; ++fi)
                ldsm4(a[fi], sb + arow + fi * 2048 + (((kc + hi16) ^ ax) << 4));
#pragma unroll
            for (int g = 0; g < 2; ++g)
                ldsm4(b[g], sb + brow + g * 2048 + (((kc + hi16) ^ ax) << 4));
#pragma unroll
            for (int fi = 0; fi < 4; ++fi)
#pragma unroll
                for (int nf = 0; nf < 4; ++nf)
                    mma16816(acc[fi][nf], a[fi], b[nf >> 1][nf & 1], b[nf >> 1][(nf & 1) + 2]);
        }
        __syncthreads();                       // stage (c%3) fully consumed
        if (c + 2 < 48 && tid == 0) issue(c + 2);
    }

    // fold bias
#pragma unroll
    for (int j = 0; j < 4; ++j) {
        float2 bv = *(const float2*)(bias + n0 + wn * 32 + j * 8 + 2 * (l & 3));
#pragma unroll
        for (int fi = 0; fi < 4; ++fi) {
            acc[fi][j][0] += bv.x; acc[fi][j][1] += bv.y;
            acc[fi][j][2] += bv.x; acc[fi][j][3] += bv.y;
        }
    }

    // ---- per-branch rank-16 correction + store (double-buffered staging) ----
    corr_load(0, base, m0, n0, tid); CPCOMMIT();
    corr_load(1, base + 16384, m0, n0, tid); CPCOMMIT();

    for (int br = 0; br < NBR; ++br) {
        uint32_t ep = base + (uint32_t)(br & 1) * 16384;
        if (br < 4) { CPWAIT(1); } else { CPWAIT(0); }
        __syncthreads();

        uint32_t b[2][4];
#pragma unroll
        for (int g = 0; g < 2; ++g) {
            int row = wn * 32 + g * 16 + (l & 15);
            uint32_t ad = ep + 8192 + (uint32_t)((row >> 2) * 128) +
                          (((uint32_t)((row & 3) * 2) + hi16) ^ (uint32_t)((row >> 2) & 1)) * 16;
            ldsm4(b[g], ad);
        }

        float* ob = out + (size_t)br * MM * NN;
#pragma unroll
        for (int h = 0; h < 2; ++h) {
            uint32_t a[2][4];
            float corr[2][4][4];
#pragma unroll
            for (int f2 = 0; f2 < 2; ++f2) {
                int fi = h * 2 + f2;
                int row = wm * 64 + fi * 16 + (l & 15);
                uint32_t ad = ep + (uint32_t)((row >> 2) * 128) +
                              (((uint32_t)((row & 3) * 2) + hi16) ^ (uint32_t)((row >> 2) & 1)) * 16;
                ldsm4(a[f2], ad);
            }
#pragma unroll
            for (int f2 = 0; f2 < 2; ++f2)
#pragma unroll
                for (int nf = 0; nf < 4; ++nf) {
#pragma unroll
                    for (int k = 0; k < 4; ++k) corr[f2][nf][k] = 0.f;
                    mma16816(corr[f2][nf], a[f2], b[nf >> 1][nf & 1], b[nf >> 1][(nf & 1) + 2]);
                }
#pragma unroll
            for (int f2 = 0; f2 < 2; ++f2) {
                int fi = h * 2 + f2;
                int mlo = m0 + wm * 64 + fi * 16 + (l >> 2);
#pragma unroll
                for (int j = 0; j < 4; ++j) {
                    int n = n0 + wn * 32 + j * 8 + 2 * (l & 3);
                    float2 v0{acc[fi][j][0] + corr[f2][j][0], acc[fi][j][1] + corr[f2][j][1]};
                    float2 v1{acc[fi][j][2] + corr[f2][j][2], acc[fi][j][3] + corr[f2][j][3]};
                    *(float2*)(ob + (size_t)mlo * NN + n) = v0;
                    *(float2*)(ob + (size_t)(mlo + 8) * NN + n) = v1;
                }
            }
        }
        __syncthreads();
        if (br + 2 < NBR) { corr_load(br + 2, ep, m0, n0, tid); CPCOMMIT(); }
    }
}

// ------------------- launcher -----------------------------------------------
extern "C" void kernel_launch(void* const* d_in, const int* in_sizes, int n_in,
                              void* d_out, int out_size)
{
    const float* x       = (const float*)d_in[0];
    const float* W       = (const float*)d_in[1];
    const float* b       = (const float*)d_in[2];
    const float* A_sh    = (const float*)d_in[3];
    const float* B_sh    = (const float*)d_in[4];
    const float* A_tasks = (const float*)d_in[5];
    const float* B_tasks = (const float*)d_in[6];
    const float* tscale  = (const float*)d_in[7];
    float* out           = (float*)d_out;

    static bool attr_done = false;
    if (!attr_done) {
        cudaFuncSetAttribute(main_kernel, cudaFuncAttributeMaxDynamicSharedMemorySize, 3 * M_STG);
        cudaFuncSetAttribute(xa_kernel,  cudaFuncAttributeMaxDynamicSharedMemorySize, 3 * XA_STG);
        attr_done = true;
    }

    split_x_k<<<MM * 128 / 256, 256>>>(x);
    split_w_k<<<NN * 128 / 256, 256>>>(W);
    conv_a_k<<<80, 256>>>(A_sh, A_tasks);
    prep_bc_k<<<20, 256>>>(B_sh, B_tasks, tscale);
    xa_kernel<<<MM / 128, 256, 3 * XA_STG>>>();
    main_kernel<<<dim3(NN / 128, MM / 256), 512, 3 * M_STG>>>(b, out);
}